// round 5
// baseline (speedup 1.0000x reference)
#include <cuda_runtime.h>
#include <cuda_bf16.h>
#include <cstddef>

#define N_NODES 50000
#define N_EDGES 800000
#define ND_IN   64
#define ED_IN   64
#define HID     128

typedef unsigned long long ull;

// ---------------- scratch (allocation-free: __device__ globals) ----------------
__device__ int   g_cnt   [N_NODES];
__device__ int   g_rowptr[N_NODES + 1];
__device__ int   g_cursor[N_NODES];
__device__ int   g_eu    [N_EDGES];
__device__ int   g_eid   [N_EDGES];
__device__ float g_msum1[(size_t)N_NODES * 128];
__device__ float g_msum2[(size_t)N_NODES * 256];
__device__ float g_hn1  [(size_t)N_NODES * HID];
__device__ float g_P    [(size_t)N_NODES * HID];  // hn @ We_top + be (bias folded)
__device__ float g_Q    [(size_t)N_NODES * HID];  // hn @ We_bot

// ---------------- packed f32x2 helpers ----------------
__device__ __forceinline__ ull pk2(float x, float y) {
    ull r; asm("mov.b64 %0, {%1, %2};" : "=l"(r) : "f"(x), "f"(y)); return r;
}
__device__ __forceinline__ void upk2(ull p, float& x, float& y) {
    asm("mov.b64 {%0, %1}, %2;" : "=f"(x), "=f"(y) : "l"(p));
}
#define FFMA2(d, a, b, c) \
    asm("fma.rn.f32x2 %0, %1, %2, %3;" : "=l"(d) : "l"(a), "l"(b), "l"(c))

// ================= CSR build =================
__global__ void cnt_kernel(const int* __restrict__ v) {
    int e = blockIdx.x * blockDim.x + threadIdx.x;
    if (e < N_EDGES) atomicAdd(&g_cnt[v[e]], 1);
}

__global__ void scan_kernel() {
    __shared__ int warp_sums[8];
    __shared__ int s_carry;
    int tid = threadIdx.x;
    int lane = tid & 31;
    int wrp = tid >> 5;
    if (tid == 0) s_carry = 0;
    __syncthreads();
    for (int base = 0; base < N_NODES; base += 256) {
        int i = base + tid;
        int x = (i < N_NODES) ? g_cnt[i] : 0;
        int vv = x;
        #pragma unroll
        for (int d = 1; d < 32; d <<= 1) {
            int t = __shfl_up_sync(0xffffffffu, vv, d);
            if (lane >= d) vv += t;
        }
        if (lane == 31) warp_sums[wrp] = vv;
        __syncthreads();
        if (tid < 8) {
            int w = warp_sums[tid];
            #pragma unroll
            for (int d = 1; d < 8; d <<= 1) {
                int t = __shfl_up_sync(0xffu, w, d);
                if (tid >= d) w += t;
            }
            warp_sums[tid] = w;
        }
        __syncthreads();
        int incl = vv + (wrp > 0 ? warp_sums[wrp - 1] : 0) + s_carry;
        if (i < N_NODES) g_rowptr[i] = incl - x;
        __syncthreads();
        if (tid == 255) s_carry = incl;
        __syncthreads();
    }
    if (tid == 0) g_rowptr[N_NODES] = s_carry;
}

__global__ void fill_kernel(const int* __restrict__ u, const int* __restrict__ v) {
    int e = blockIdx.x * blockDim.x + threadIdx.x;
    if (e >= N_EDGES) return;
    int pos = atomicAdd(&g_cursor[v[e]], 1);
    g_eu[pos]  = u[e];
    g_eid[pos] = e;
}

// ================= layer-1 aggregation (gather, warp per node, unroll-2) =================
__global__ void agg1_kernel(const float* __restrict__ nf,
                            const float* __restrict__ ef) {
    int gtid = blockIdx.x * blockDim.x + threadIdx.x;
    int node = gtid >> 5;
    int lane = gtid & 31;
    if (node >= N_NODES) return;
    int beg = g_rowptr[node], end = g_rowptr[node + 1];
    int c = lane * 4;
    bool isn = (lane < 16);
    int coff = isn ? c : (c - ND_IN);

    float4 acc0 = make_float4(0.f, 0.f, 0.f, 0.f);
    float4 acc1 = make_float4(0.f, 0.f, 0.f, 0.f);
    int i = beg;
    for (; i + 1 < end; i += 2) {
        int ia = isn ? g_eu[i]     : g_eid[i];
        int ib = isn ? g_eu[i + 1] : g_eid[i + 1];
        const float* base = isn ? nf : ef;
        float4 t0 = *(const float4*)(base + (size_t)ia * 64 + coff);
        float4 t1 = *(const float4*)(base + (size_t)ib * 64 + coff);
        acc0.x += t0.x; acc0.y += t0.y; acc0.z += t0.z; acc0.w += t0.w;
        acc1.x += t1.x; acc1.y += t1.y; acc1.z += t1.z; acc1.w += t1.w;
    }
    if (i < end) {
        int ia = isn ? g_eu[i] : g_eid[i];
        const float* base = isn ? nf : ef;
        float4 t0 = *(const float4*)(base + (size_t)ia * 64 + coff);
        acc0.x += t0.x; acc0.y += t0.y; acc0.z += t0.z; acc0.w += t0.w;
    }
    acc0.x += acc1.x; acc0.y += acc1.y; acc0.z += acc1.z; acc0.w += acc1.w;
    *(float4*)&g_msum1[(size_t)node * 128 + c] = acc0;
}

// ================= layer-2 aggregation fused with edge-1 MLP (gather, unroll-2) ===========
// msum2[v][0:128] = sum hn1[u];  msum2[v][128:256] = sum relu(P[u] + Q[v])  (bias in P)
__global__ void agg2_kernel() {
    int gtid = blockIdx.x * blockDim.x + threadIdx.x;
    int node = gtid >> 5;
    int lane = gtid & 31;
    if (node >= N_NODES) return;
    int beg = g_rowptr[node], end = g_rowptr[node + 1];
    int c = lane * 4;

    float4 qb = *(const float4*)&g_Q[(size_t)node * HID + c];

    float4 aH0 = make_float4(0.f, 0.f, 0.f, 0.f);
    float4 aH1 = make_float4(0.f, 0.f, 0.f, 0.f);
    float4 aE0 = make_float4(0.f, 0.f, 0.f, 0.f);
    float4 aE1 = make_float4(0.f, 0.f, 0.f, 0.f);
    int i = beg;
    for (; i + 1 < end; i += 2) {
        int ua = g_eu[i], ub = g_eu[i + 1];
        float4 h0 = *(const float4*)&g_hn1[(size_t)ua * HID + c];
        float4 p0 = *(const float4*)&g_P  [(size_t)ua * HID + c];
        float4 h1 = *(const float4*)&g_hn1[(size_t)ub * HID + c];
        float4 p1 = *(const float4*)&g_P  [(size_t)ub * HID + c];
        aH0.x += h0.x; aH0.y += h0.y; aH0.z += h0.z; aH0.w += h0.w;
        aH1.x += h1.x; aH1.y += h1.y; aH1.z += h1.z; aH1.w += h1.w;
        aE0.x += fmaxf(p0.x + qb.x, 0.f); aE0.y += fmaxf(p0.y + qb.y, 0.f);
        aE0.z += fmaxf(p0.z + qb.z, 0.f); aE0.w += fmaxf(p0.w + qb.w, 0.f);
        aE1.x += fmaxf(p1.x + qb.x, 0.f); aE1.y += fmaxf(p1.y + qb.y, 0.f);
        aE1.z += fmaxf(p1.z + qb.z, 0.f); aE1.w += fmaxf(p1.w + qb.w, 0.f);
    }
    if (i < end) {
        int ua = g_eu[i];
        float4 h0 = *(const float4*)&g_hn1[(size_t)ua * HID + c];
        float4 p0 = *(const float4*)&g_P  [(size_t)ua * HID + c];
        aH0.x += h0.x; aH0.y += h0.y; aH0.z += h0.z; aH0.w += h0.w;
        aE0.x += fmaxf(p0.x + qb.x, 0.f); aE0.y += fmaxf(p0.y + qb.y, 0.f);
        aE0.z += fmaxf(p0.z + qb.z, 0.f); aE0.w += fmaxf(p0.w + qb.w, 0.f);
    }
    aH0.x += aH1.x; aH0.y += aH1.y; aH0.z += aH1.z; aH0.w += aH1.w;
    aE0.x += aE1.x; aE0.y += aE1.y; aE0.z += aE1.z; aE0.w += aE1.w;
    *(float4*)&g_msum2[(size_t)node * 256 + c]       = aH0;
    *(float4*)&g_msum2[(size_t)node * 256 + 128 + c] = aE0;
}

// ================= node apply: out = relu(concat(hn, msum/deg) @ W + b) =================
// NPB=32, 128 threads = 2 groups x 64 col-threads; 8 node-pairs x 2 cols per thread.
template <int KN, int KM>
__global__ void __launch_bounds__(128)
node_apply_kernel(const float* __restrict__ hn,
                  const float* __restrict__ msum,
                  const float* __restrict__ W,
                  const float* __restrict__ b,
                  float* __restrict__ out) {
    constexpr int K = KN + KM;
    constexpr int NPB = 32;
    __shared__ float xs[K][NPB + 2];
    __shared__ float rdeg_s[NPB];
    int n0 = blockIdx.x * NPB;
    int tid = threadIdx.x;

    if (tid < NPB) {
        int n = n0 + tid;
        float d = 1.0f;
        if (n < N_NODES) d = (float)max(g_rowptr[n + 1] - g_rowptr[n], 1);
        rdeg_s[tid] = 1.0f / d;
    }
    __syncthreads();

    for (int idx = tid; idx < NPB * K; idx += 128) {
        int ni = idx / K;
        int k  = idx % K;
        int n  = n0 + ni;
        float val = 0.0f;
        if (n < N_NODES) {
            if (k < KN) val = hn[(size_t)n * KN + k];
            else        val = msum[(size_t)n * KM + (k - KN)] * rdeg_s[ni];
        }
        xs[k][ni] = val;
    }
    __syncthreads();

    int grp = tid >> 6;
    int jt  = tid & 63;
    float b0 = b[jt], b1 = b[jt + 64];
    ull a0[8], a1[8];
    #pragma unroll
    for (int i = 0; i < 8; i++) { a0[i] = pk2(b0, b0); a1[i] = pk2(b1, b1); }

    const float* Wj = W + jt;
    #pragma unroll 2
    for (int k = 0; k < K; k++) {
        float w0 = Wj[k * HID];
        float w1 = Wj[k * HID + 64];
        ull w0d = pk2(w0, w0);
        ull w1d = pk2(w1, w1);
        ull xp[8];
        #pragma unroll
        for (int i = 0; i < 8; i++)
            xp[i] = *(const ull*)&xs[k][grp * 16 + 2 * i];
        #pragma unroll
        for (int i = 0; i < 8; i++) {
            FFMA2(a0[i], xp[i], w0d, a0[i]);
            FFMA2(a1[i], xp[i], w1d, a1[i]);
        }
    }
    #pragma unroll
    for (int i = 0; i < 8; i++) {
        int n = n0 + grp * 16 + 2 * i;
        float x0, x1, y0, y1;
        upk2(a0[i], x0, x1);
        upk2(a1[i], y0, y1);
        if (n < N_NODES) {
            out[(size_t)n * HID + jt]      = fmaxf(x0, 0.0f);
            out[(size_t)n * HID + jt + 64] = fmaxf(y0, 0.0f);
        }
        if (n + 1 < N_NODES) {
            out[(size_t)(n + 1) * HID + jt]      = fmaxf(x1, 0.0f);
            out[(size_t)(n + 1) * HID + jt + 64] = fmaxf(y1, 0.0f);
        }
    }
}

// ================= P/Q projection (bias folded into P) =================
__global__ void __launch_bounds__(128)
pq_gemm_kernel(const float* __restrict__ hn,
               const float* __restrict__ W,   // [256,128] row-major
               const float* __restrict__ be,
               float* __restrict__ P,
               float* __restrict__ Q) {
    constexpr int NPB = 32;
    __shared__ float xs[HID][NPB + 2];
    int n0 = blockIdx.x * NPB;
    int tid = threadIdx.x;

    for (int idx = tid; idx < NPB * HID; idx += 128) {
        int ni = idx >> 7;
        int k  = idx & 127;
        int n  = n0 + ni;
        xs[k][ni] = (n < N_NODES) ? hn[(size_t)n * HID + k] : 0.0f;
    }
    __syncthreads();

    int grp = tid >> 6;
    int jt  = tid & 63;
    float be0 = be[jt], be1 = be[jt + 64];
    ull p0[8], p1[8], q0[8], q1[8];
    #pragma unroll
    for (int i = 0; i < 8; i++) {
        p0[i] = pk2(be0, be0);
        p1[i] = pk2(be1, be1);
        q0[i] = 0ull; q1[i] = 0ull;
    }

    const float* Wj = W + jt;
    #pragma unroll 2
    for (int k = 0; k < HID; k++) {
        float wt0 = Wj[k * HID];
        float wt1 = Wj[k * HID + 64];
        float wb0 = Wj[(k + HID) * HID];
        float wb1 = Wj[(k + HID) * HID + 64];
        ull wt0d = pk2(wt0, wt0);
        ull wt1d = pk2(wt1, wt1);
        ull wb0d = pk2(wb0, wb0);
        ull wb1d = pk2(wb1, wb1);
        ull xp[8];
        #pragma unroll
        for (int i = 0; i < 8; i++)
            xp[i] = *(const ull*)&xs[k][grp * 16 + 2 * i];
        #pragma unroll
        for (int i = 0; i < 8; i++) {
            FFMA2(p0[i], xp[i], wt0d, p0[i]);
            FFMA2(p1[i], xp[i], wt1d, p1[i]);
            FFMA2(q0[i], xp[i], wb0d, q0[i]);
            FFMA2(q1[i], xp[i], wb1d, q1[i]);
        }
    }
    #pragma unroll
    for (int i = 0; i < 8; i++) {
        int n = n0 + grp * 16 + 2 * i;
        float x0, x1;
        if (n < N_NODES) {
            upk2(p0[i], x0, x1); P[(size_t)n * HID + jt] = x0;
            upk2(p1[i], x0, x1); P[(size_t)n * HID + jt + 64] = x0;
            upk2(q0[i], x0, x1); Q[(size_t)n * HID + jt] = x0;
            upk2(q1[i], x0, x1); Q[(size_t)n * HID + jt + 64] = x0;
        }
        if (n + 1 < N_NODES) {
            upk2(p0[i], x0, x1); P[(size_t)(n + 1) * HID + jt] = x1;
            upk2(p1[i], x0, x1); P[(size_t)(n + 1) * HID + jt + 64] = x1;
            upk2(q0[i], x0, x1); Q[(size_t)(n + 1) * HID + jt] = x1;
            upk2(q1[i], x0, x1); Q[(size_t)(n + 1) * HID + jt + 64] = x1;
        }
    }
}

// ================= layer-2 edge: he2 = relu(P[u]+Q[v]) -> out (bias in P) =================
__global__ void edge2_kernel(const int* __restrict__ u,
                             const int* __restrict__ v,
                             float* __restrict__ he2) {
    int gtid = blockIdx.x * blockDim.x + threadIdx.x;
    int e = gtid >> 5;
    int lane = gtid & 31;
    if (e >= N_EDGES) return;
    int un = u[e], vn = v[e];
    int c = lane * 4;

    float4 p = *(const float4*)&g_P[(size_t)un * HID + c];
    float4 q = *(const float4*)&g_Q[(size_t)vn * HID + c];
    float4 h;
    h.x = fmaxf(p.x + q.x, 0.f);
    h.y = fmaxf(p.y + q.y, 0.f);
    h.z = fmaxf(p.z + q.z, 0.f);
    h.w = fmaxf(p.w + q.w, 0.f);
    *(float4*)&he2[(size_t)e * HID + c] = h;
}

// ---------------- launch ----------------
extern "C" void kernel_launch(void* const* d_in, const int* in_sizes, int n_in,
                              void* d_out, int out_size) {
    const float* nfeats = (const float*)d_in[0];
    const float* efeats = (const float*)d_in[1];
    const float* W1a_w  = (const float*)d_in[2];
    const float* W1a_b  = (const float*)d_in[3];
    const float* W1e_w  = (const float*)d_in[4];
    const float* W1e_b  = (const float*)d_in[5];
    const float* W2a_w  = (const float*)d_in[6];
    const float* W2a_b  = (const float*)d_in[7];
    const float* W2e_w  = (const float*)d_in[8];
    const float* W2e_b  = (const float*)d_in[9];
    const int*   u      = (const int*)d_in[10];
    const int*   v      = (const int*)d_in[11];

    float* out = (float*)d_out;
    float* hn2 = out;                          // [N, 128]
    float* he2 = out + (size_t)N_NODES * HID;  // [E, 128]

    void *p_cnt, *p_rowptr, *p_cursor, *p_m1, *p_m2, *p_hn1, *p_P, *p_Q;
    cudaGetSymbolAddress(&p_cnt,    g_cnt);
    cudaGetSymbolAddress(&p_rowptr, g_rowptr);
    cudaGetSymbolAddress(&p_cursor, g_cursor);
    cudaGetSymbolAddress(&p_m1,     g_msum1);
    cudaGetSymbolAddress(&p_m2,     g_msum2);
    cudaGetSymbolAddress(&p_hn1,    g_hn1);
    cudaGetSymbolAddress(&p_P,      g_P);
    cudaGetSymbolAddress(&p_Q,      g_Q);
    float* msum1 = (float*)p_m1;
    float* msum2 = (float*)p_m2;
    float* hn1   = (float*)p_hn1;
    float* P     = (float*)p_P;
    float* Q     = (float*)p_Q;

    const int EBLK  = (N_EDGES + 255) / 256;
    const int WBLK  = (N_EDGES * 32 + 255) / 256;
    const int NWBLK = (N_NODES * 32 + 255) / 256;
    const int GBLK  = (N_NODES + 31) / 32;     // 1563 GEMM blocks

    // ---- CSR build ----
    cudaMemsetAsync(p_cnt, 0, sizeof(int) * N_NODES, 0);
    cnt_kernel<<<EBLK, 256>>>(v);
    scan_kernel<<<1, 256>>>();
    cudaMemcpyAsync(p_cursor, p_rowptr, sizeof(int) * N_NODES,
                    cudaMemcpyDeviceToDevice, 0);
    fill_kernel<<<EBLK, 256>>>(u, v);

    // ---- layer 1 ----
    agg1_kernel<<<NWBLK, 256>>>(nfeats, efeats);
    node_apply_kernel<ND_IN, ND_IN + ED_IN><<<GBLK, 128>>>(nfeats, msum1, W1a_w, W1a_b, hn1);
    pq_gemm_kernel<<<GBLK, 128>>>(hn1, W1e_w, W1e_b, P, Q);
    agg2_kernel<<<NWBLK, 256>>>();

    // ---- layer 2 ----
    node_apply_kernel<HID, 2 * HID><<<GBLK, 128>>>(hn1, msum2, W2a_w, W2a_b, hn2);
    pq_gemm_kernel<<<GBLK, 128>>>(hn2, W2e_w, W2e_b, P, Q);
    edge2_kernel<<<WBLK, 256>>>(u, v, he2);
}

// round 6
// speedup vs baseline: 1.2116x; 1.2116x over previous
#include <cuda_runtime.h>
#include <cuda_bf16.h>
#include <cstddef>

#define N_NODES 50000
#define N_EDGES 800000
#define ND_IN   64
#define ED_IN   64
#define HID     128

typedef unsigned long long ull;

// ---------------- scratch (allocation-free: __device__ globals) ----------------
__device__ int   g_cnt   [N_NODES];
__device__ int   g_rowptr[N_NODES + 1];
__device__ int   g_cursor[N_NODES];
__device__ int   g_eu    [N_EDGES];
__device__ int   g_eid   [N_EDGES];
__device__ float g_msum1[(size_t)N_NODES * 128];
__device__ float g_msum2[(size_t)N_NODES * 256];
__device__ float g_hn1  [(size_t)N_NODES * HID];
__device__ float g_P    [(size_t)N_NODES * HID];  // hn @ We_top + be (bias folded)
__device__ float g_Q    [(size_t)N_NODES * HID];  // hn @ We_bot

// ---------------- packed f32x2 helpers ----------------
__device__ __forceinline__ ull pk2(float x, float y) {
    ull r; asm("mov.b64 %0, {%1, %2};" : "=l"(r) : "f"(x), "f"(y)); return r;
}
__device__ __forceinline__ void upk2(ull p, float& x, float& y) {
    asm("mov.b64 {%0, %1}, %2;" : "=f"(x), "=f"(y) : "l"(p));
}
#define FFMA2(d, a, b, c) \
    asm("fma.rn.f32x2 %0, %1, %2, %3;" : "=l"(d) : "l"(a), "l"(b), "l"(c))

// ================= CSR build =================
__global__ void cnt_kernel(const int* __restrict__ v) {
    int e = blockIdx.x * blockDim.x + threadIdx.x;
    if (e < N_EDGES) atomicAdd(&g_cnt[v[e]], 1);
}

__global__ void scan_kernel() {
    __shared__ int warp_sums[8];
    __shared__ int s_carry;
    int tid = threadIdx.x;
    int lane = tid & 31;
    int wrp = tid >> 5;
    if (tid == 0) s_carry = 0;
    __syncthreads();
    for (int base = 0; base < N_NODES; base += 256) {
        int i = base + tid;
        int x = (i < N_NODES) ? g_cnt[i] : 0;
        int vv = x;
        #pragma unroll
        for (int d = 1; d < 32; d <<= 1) {
            int t = __shfl_up_sync(0xffffffffu, vv, d);
            if (lane >= d) vv += t;
        }
        if (lane == 31) warp_sums[wrp] = vv;
        __syncthreads();
        if (tid < 8) {
            int w = warp_sums[tid];
            #pragma unroll
            for (int d = 1; d < 8; d <<= 1) {
                int t = __shfl_up_sync(0xffu, w, d);
                if (tid >= d) w += t;
            }
            warp_sums[tid] = w;
        }
        __syncthreads();
        int incl = vv + (wrp > 0 ? warp_sums[wrp - 1] : 0) + s_carry;
        if (i < N_NODES) g_rowptr[i] = incl - x;
        __syncthreads();
        if (tid == 255) s_carry = incl;
        __syncthreads();
    }
    if (tid == 0) g_rowptr[N_NODES] = s_carry;
}

__global__ void fill_kernel(const int* __restrict__ u, const int* __restrict__ v) {
    int e = blockIdx.x * blockDim.x + threadIdx.x;
    if (e >= N_EDGES) return;
    int pos = atomicAdd(&g_cursor[v[e]], 1);
    g_eu[pos]  = u[e];
    g_eid[pos] = e;
}

// ================= layer-1 aggregation (gather, warp per node) — R4 proven form =========
__global__ void agg1_kernel(const float* __restrict__ nf,
                            const float* __restrict__ ef) {
    int gtid = blockIdx.x * blockDim.x + threadIdx.x;
    int node = gtid >> 5;
    int lane = gtid & 31;
    if (node >= N_NODES) return;
    int beg = g_rowptr[node], end = g_rowptr[node + 1];
    int c = lane * 4;
    float4 acc = make_float4(0.f, 0.f, 0.f, 0.f);
    for (int i = beg; i < end; i++) {
        const float4* src;
        if (lane < 16)
            src = (const float4*)(nf + (size_t)g_eu[i] * ND_IN + c);
        else
            src = (const float4*)(ef + (size_t)g_eid[i] * ED_IN + (c - ND_IN));
        float4 t = *src;
        acc.x += t.x; acc.y += t.y; acc.z += t.z; acc.w += t.w;
    }
    *(float4*)&g_msum1[(size_t)node * 128 + c] = acc;
}

// ================= layer-2 aggregation fused with edge-1 MLP (bias folded into P) =========
// msum2[v][0:128] = sum hn1[u];  msum2[v][128:256] = sum relu(P[u] + Q[v])
__global__ void agg2_kernel() {
    int gtid = blockIdx.x * blockDim.x + threadIdx.x;
    int node = gtid >> 5;
    int lane = gtid & 31;
    if (node >= N_NODES) return;
    int beg = g_rowptr[node], end = g_rowptr[node + 1];
    int c = lane * 4;

    float4 qb = *(const float4*)&g_Q[(size_t)node * HID + c];

    float4 accH = make_float4(0.f, 0.f, 0.f, 0.f);
    float4 accE = make_float4(0.f, 0.f, 0.f, 0.f);
    for (int i = beg; i < end; i++) {
        int un = g_eu[i];
        float4 hu = *(const float4*)&g_hn1[(size_t)un * HID + c];
        float4 p  = *(const float4*)&g_P[(size_t)un * HID + c];
        accH.x += hu.x; accH.y += hu.y; accH.z += hu.z; accH.w += hu.w;
        accE.x += fmaxf(p.x + qb.x, 0.f);
        accE.y += fmaxf(p.y + qb.y, 0.f);
        accE.z += fmaxf(p.z + qb.z, 0.f);
        accE.w += fmaxf(p.w + qb.w, 0.f);
    }
    *(float4*)&g_msum2[(size_t)node * 256 + c]       = accH;
    *(float4*)&g_msum2[(size_t)node * 256 + 128 + c] = accE;
}

// ================= node apply: out = relu(concat(hn, msum*rdeg) @ W + b) =================
// R4 proven shape: NPB=16, 128 threads, xs[K][18]; + rdeg precompute in smem.
template <int KN, int KM>
__global__ void __launch_bounds__(128)
node_apply_kernel(const float* __restrict__ hn,
                  const float* __restrict__ msum,
                  const float* __restrict__ W,
                  const float* __restrict__ b,
                  float* __restrict__ out) {
    constexpr int K = KN + KM;
    constexpr int NPB = 16;
    __shared__ float xs[K][18];
    __shared__ float rdeg_s[NPB];
    int n0 = blockIdx.x * NPB;
    int tid = threadIdx.x;

    if (tid < NPB) {
        int n = n0 + tid;
        float d = (float)max(g_rowptr[n + 1] - g_rowptr[n], 1);
        rdeg_s[tid] = 1.0f / d;
    }
    __syncthreads();

    for (int idx = tid; idx < NPB * K; idx += 128) {
        int ni = idx / K;
        int k  = idx % K;
        int n  = n0 + ni;
        float val;
        if (k < KN) val = hn[(size_t)n * KN + k];
        else        val = msum[(size_t)n * KM + (k - KN)] * rdeg_s[ni];
        xs[k][ni] = val;
    }
    __syncthreads();

    int grp = tid >> 6;
    int jt  = tid & 63;
    float b0 = b[jt], b1 = b[jt + 64];
    ull a0[4], a1[4];
    #pragma unroll
    for (int i = 0; i < 4; i++) { a0[i] = pk2(b0, b0); a1[i] = pk2(b1, b1); }

    const float* Wj = W + jt;
    #pragma unroll 4
    for (int k = 0; k < K; k++) {
        float w0 = Wj[k * HID];
        float w1 = Wj[k * HID + 64];
        ull w0d = pk2(w0, w0);
        ull w1d = pk2(w1, w1);
        ull xp[4];
        #pragma unroll
        for (int i = 0; i < 4; i++)
            xp[i] = *(const ull*)&xs[k][grp * 8 + 2 * i];
        #pragma unroll
        for (int i = 0; i < 4; i++) {
            FFMA2(a0[i], xp[i], w0d, a0[i]);
            FFMA2(a1[i], xp[i], w1d, a1[i]);
        }
    }
    #pragma unroll
    for (int i = 0; i < 4; i++) {
        float x0, x1, y0, y1;
        upk2(a0[i], x0, x1);
        upk2(a1[i], y0, y1);
        size_t n = (size_t)(n0 + grp * 8 + 2 * i);
        out[n * HID + jt]            = fmaxf(x0, 0.0f);
        out[(n + 1) * HID + jt]      = fmaxf(x1, 0.0f);
        out[n * HID + jt + 64]       = fmaxf(y0, 0.0f);
        out[(n + 1) * HID + jt + 64] = fmaxf(y1, 0.0f);
    }
}

// ================= P/Q projection (bias folded into P) — R4 proven shape =================
__global__ void __launch_bounds__(128)
pq_gemm_kernel(const float* __restrict__ hn,
               const float* __restrict__ W,   // [256,128] row-major
               const float* __restrict__ be,
               float* __restrict__ P,
               float* __restrict__ Q) {
    constexpr int NPB = 16;
    __shared__ float xs[HID][18];
    int n0 = blockIdx.x * NPB;
    int tid = threadIdx.x;

    for (int idx = tid; idx < NPB * HID; idx += 128) {
        int ni = idx >> 7;
        int k  = idx & 127;
        xs[k][ni] = hn[(size_t)(n0 + ni) * HID + k];
    }
    __syncthreads();

    int grp = tid >> 6;
    int jt  = tid & 63;
    float be0 = be[jt], be1 = be[jt + 64];
    ull p0[4], p1[4], q0[4], q1[4];
    #pragma unroll
    for (int i = 0; i < 4; i++) {
        p0[i] = pk2(be0, be0);
        p1[i] = pk2(be1, be1);
        q0[i] = 0ull; q1[i] = 0ull;
    }

    const float* Wj = W + jt;
    #pragma unroll 2
    for (int k = 0; k < HID; k++) {
        float wt0 = Wj[k * HID];
        float wt1 = Wj[k * HID + 64];
        float wb0 = Wj[(k + HID) * HID];
        float wb1 = Wj[(k + HID) * HID + 64];
        ull wt0d = pk2(wt0, wt0);
        ull wt1d = pk2(wt1, wt1);
        ull wb0d = pk2(wb0, wb0);
        ull wb1d = pk2(wb1, wb1);
        ull xp[4];
        #pragma unroll
        for (int i = 0; i < 4; i++)
            xp[i] = *(const ull*)&xs[k][grp * 8 + 2 * i];
        #pragma unroll
        for (int i = 0; i < 4; i++) {
            FFMA2(p0[i], xp[i], wt0d, p0[i]);
            FFMA2(p1[i], xp[i], wt1d, p1[i]);
            FFMA2(q0[i], xp[i], wb0d, q0[i]);
            FFMA2(q1[i], xp[i], wb1d, q1[i]);
        }
    }
    #pragma unroll
    for (int i = 0; i < 4; i++) {
        float x0, x1;
        size_t n = (size_t)(n0 + grp * 8 + 2 * i);
        upk2(p0[i], x0, x1); P[n * HID + jt]      = x0; P[(n + 1) * HID + jt]      = x1;
        upk2(p1[i], x0, x1); P[n * HID + jt + 64] = x0; P[(n + 1) * HID + jt + 64] = x1;
        upk2(q0[i], x0, x1); Q[n * HID + jt]      = x0; Q[(n + 1) * HID + jt]      = x1;
        upk2(q1[i], x0, x1); Q[n * HID + jt + 64] = x0; Q[(n + 1) * HID + jt + 64] = x1;
    }
}

// ================= layer-2 edge via CSR: he2[eid] = relu(P[u]+Q[v]) =================
// warp per dst node: Q2[v] loaded once into registers; per edge read only P2[u],
// write the (row-coalesced) output row at the original edge id.
__global__ void edge2_csr_kernel(float* __restrict__ he2) {
    int gtid = blockIdx.x * blockDim.x + threadIdx.x;
    int node = gtid >> 5;
    int lane = gtid & 31;
    if (node >= N_NODES) return;
    int beg = g_rowptr[node], end = g_rowptr[node + 1];
    int c = lane * 4;

    float4 qb = *(const float4*)&g_Q[(size_t)node * HID + c];

    for (int i = beg; i < end; i++) {
        int un  = g_eu[i];
        int eid = g_eid[i];
        float4 p = *(const float4*)&g_P[(size_t)un * HID + c];
        float4 h;
        h.x = fmaxf(p.x + qb.x, 0.f);
        h.y = fmaxf(p.y + qb.y, 0.f);
        h.z = fmaxf(p.z + qb.z, 0.f);
        h.w = fmaxf(p.w + qb.w, 0.f);
        *(float4*)&he2[(size_t)eid * HID + c] = h;
    }
}

// ---------------- launch ----------------
extern "C" void kernel_launch(void* const* d_in, const int* in_sizes, int n_in,
                              void* d_out, int out_size) {
    const float* nfeats = (const float*)d_in[0];
    const float* efeats = (const float*)d_in[1];
    const float* W1a_w  = (const float*)d_in[2];
    const float* W1a_b  = (const float*)d_in[3];
    const float* W1e_w  = (const float*)d_in[4];
    const float* W1e_b  = (const float*)d_in[5];
    const float* W2a_w  = (const float*)d_in[6];
    const float* W2a_b  = (const float*)d_in[7];
    const float* W2e_w  = (const float*)d_in[8];
    const float* W2e_b  = (const float*)d_in[9];
    const int*   u      = (const int*)d_in[10];
    const int*   v      = (const int*)d_in[11];

    float* out = (float*)d_out;
    float* hn2 = out;                          // [N, 128]
    float* he2 = out + (size_t)N_NODES * HID;  // [E, 128]

    void *p_cnt, *p_rowptr, *p_cursor, *p_m1, *p_m2, *p_hn1, *p_P, *p_Q;
    cudaGetSymbolAddress(&p_cnt,    g_cnt);
    cudaGetSymbolAddress(&p_rowptr, g_rowptr);
    cudaGetSymbolAddress(&p_cursor, g_cursor);
    cudaGetSymbolAddress(&p_m1,     g_msum1);
    cudaGetSymbolAddress(&p_m2,     g_msum2);
    cudaGetSymbolAddress(&p_hn1,    g_hn1);
    cudaGetSymbolAddress(&p_P,      g_P);
    cudaGetSymbolAddress(&p_Q,      g_Q);
    float* msum1 = (float*)p_m1;
    float* msum2 = (float*)p_m2;
    float* hn1   = (float*)p_hn1;
    float* P     = (float*)p_P;
    float* Q     = (float*)p_Q;

    const int EBLK  = (N_EDGES + 255) / 256;
    const int NWBLK = (N_NODES * 32 + 255) / 256;
    const int GBLK  = N_NODES / 16;            // 3125 (50000 % 16 == 0)

    // ---- CSR build ----
    cudaMemsetAsync(p_cnt, 0, sizeof(int) * N_NODES, 0);
    cnt_kernel<<<EBLK, 256>>>(v);
    scan_kernel<<<1, 256>>>();
    cudaMemcpyAsync(p_cursor, p_rowptr, sizeof(int) * N_NODES,
                    cudaMemcpyDeviceToDevice, 0);
    fill_kernel<<<EBLK, 256>>>(u, v);

    // ---- layer 1 ----
    agg1_kernel<<<NWBLK, 256>>>(nfeats, efeats);
    node_apply_kernel<ND_IN, ND_IN + ED_IN><<<GBLK, 128>>>(nfeats, msum1, W1a_w, W1a_b, hn1);
    pq_gemm_kernel<<<GBLK, 128>>>(hn1, W1e_w, W1e_b, P, Q);
    agg2_kernel<<<NWBLK, 256>>>();

    // ---- layer 2 ----
    node_apply_kernel<HID, 2 * HID><<<GBLK, 128>>>(hn1, msum2, W2a_w, W2a_b, hn2);
    pq_gemm_kernel<<<GBLK, 128>>>(hn2, W2e_w, W2e_b, P, Q);
    edge2_csr_kernel<<<NWBLK, 256>>>(he2);
}

// round 7
// speedup vs baseline: 1.3537x; 1.1172x over previous
#include <cuda_runtime.h>
#include <cuda_bf16.h>
#include <cstddef>

#define N_NODES 50000
#define N_EDGES 800000
#define ND_IN   64
#define ED_IN   64
#define HID     128

typedef unsigned long long ull;

// ---------------- scratch (allocation-free: __device__ globals) ----------------
__device__ int   g_cnt   [N_NODES];
__device__ int   g_rowptr[N_NODES + 1];
__device__ int   g_cursor[N_NODES];
__device__ int   g_eu    [N_EDGES];
__device__ int   g_eid   [N_EDGES];
__device__ float g_msum1[(size_t)N_NODES * 128];
__device__ float g_msum2[(size_t)N_NODES * 256];
__device__ float g_hn1  [(size_t)N_NODES * HID];
__device__ float g_P    [(size_t)N_NODES * HID];  // hn @ We_top + be (bias folded)
__device__ float g_Q    [(size_t)N_NODES * HID];  // hn @ We_bot

// ---------------- packed f32x2 helpers ----------------
__device__ __forceinline__ ull pk2(float x, float y) {
    ull r; asm("mov.b64 %0, {%1, %2};" : "=l"(r) : "f"(x), "f"(y)); return r;
}
__device__ __forceinline__ void upk2(ull p, float& x, float& y) {
    asm("mov.b64 {%0, %1}, %2;" : "=f"(x), "=f"(y) : "l"(p));
}
#define FFMA2(d, a, b, c) \
    asm("fma.rn.f32x2 %0, %1, %2, %3;" : "=l"(d) : "l"(a), "l"(b), "l"(c))

// ================= CSR build =================
__global__ void cnt_kernel(const int* __restrict__ v) {
    int e = blockIdx.x * blockDim.x + threadIdx.x;
    if (e < N_EDGES) atomicAdd(&g_cnt[v[e]], 1);
}

__global__ void scan_kernel() {
    __shared__ int warp_sums[8];
    __shared__ int s_carry;
    int tid = threadIdx.x;
    int lane = tid & 31;
    int wrp = tid >> 5;
    if (tid == 0) s_carry = 0;
    __syncthreads();
    for (int base = 0; base < N_NODES; base += 256) {
        int i = base + tid;
        int x = (i < N_NODES) ? g_cnt[i] : 0;
        int vv = x;
        #pragma unroll
        for (int d = 1; d < 32; d <<= 1) {
            int t = __shfl_up_sync(0xffffffffu, vv, d);
            if (lane >= d) vv += t;
        }
        if (lane == 31) warp_sums[wrp] = vv;
        __syncthreads();
        if (tid < 8) {
            int w = warp_sums[tid];
            #pragma unroll
            for (int d = 1; d < 8; d <<= 1) {
                int t = __shfl_up_sync(0xffu, w, d);
                if (tid >= d) w += t;
            }
            warp_sums[tid] = w;
        }
        __syncthreads();
        int incl = vv + (wrp > 0 ? warp_sums[wrp - 1] : 0) + s_carry;
        if (i < N_NODES) g_rowptr[i] = incl - x;
        __syncthreads();
        if (tid == 255) s_carry = incl;
        __syncthreads();
    }
    if (tid == 0) g_rowptr[N_NODES] = s_carry;
}

__global__ void fill_kernel(const int* __restrict__ u, const int* __restrict__ v) {
    int e = blockIdx.x * blockDim.x + threadIdx.x;
    if (e >= N_EDGES) return;
    int pos = atomicAdd(&g_cursor[v[e]], 1);
    g_eu[pos]  = u[e];
    g_eid[pos] = e;
}

// ================= layer-1 aggregation (gather, warp per node, unroll-2, occ-pinned) ======
__global__ void __launch_bounds__(256, 8)
agg1_kernel(const float* __restrict__ nf,
            const float* __restrict__ ef) {
    int gtid = blockIdx.x * blockDim.x + threadIdx.x;
    int node = gtid >> 5;
    int lane = gtid & 31;
    if (node >= N_NODES) return;
    int beg = g_rowptr[node], end = g_rowptr[node + 1];
    int c = lane * 4;
    bool isn = (lane < 16);
    const float* base = isn ? nf : ef;
    int coff = isn ? c : (c - ND_IN);
    const int* idxa = isn ? g_eu : g_eid;

    float4 acc = make_float4(0.f, 0.f, 0.f, 0.f);
    int i = beg;
    for (; i + 1 < end; i += 2) {
        int ia = idxa[i];
        int ib = idxa[i + 1];
        float4 t0 = *(const float4*)(base + (size_t)ia * 64 + coff);
        float4 t1 = *(const float4*)(base + (size_t)ib * 64 + coff);
        acc.x += t0.x + t1.x;
        acc.y += t0.y + t1.y;
        acc.z += t0.z + t1.z;
        acc.w += t0.w + t1.w;
    }
    if (i < end) {
        int ia = idxa[i];
        float4 t0 = *(const float4*)(base + (size_t)ia * 64 + coff);
        acc.x += t0.x; acc.y += t0.y; acc.z += t0.z; acc.w += t0.w;
    }
    *(float4*)&g_msum1[(size_t)node * 128 + c] = acc;
}

// ================= layer-2 aggregation fused with edge-1 MLP (unroll-2, occ-pinned) =======
// msum2[v][0:128] = sum hn1[u];  msum2[v][128:256] = sum relu(P[u] + Q[v])  (bias in P)
__global__ void __launch_bounds__(256, 8)
agg2_kernel() {
    int gtid = blockIdx.x * blockDim.x + threadIdx.x;
    int node = gtid >> 5;
    int lane = gtid & 31;
    if (node >= N_NODES) return;
    int beg = g_rowptr[node], end = g_rowptr[node + 1];
    int c = lane * 4;

    float4 qb = *(const float4*)&g_Q[(size_t)node * HID + c];

    float4 accH = make_float4(0.f, 0.f, 0.f, 0.f);
    float4 accE = make_float4(0.f, 0.f, 0.f, 0.f);
    int i = beg;
    for (; i + 1 < end; i += 2) {
        int ua = g_eu[i], ub = g_eu[i + 1];
        float4 h0 = *(const float4*)&g_hn1[(size_t)ua * HID + c];
        float4 p0 = *(const float4*)&g_P  [(size_t)ua * HID + c];
        float4 h1 = *(const float4*)&g_hn1[(size_t)ub * HID + c];
        float4 p1 = *(const float4*)&g_P  [(size_t)ub * HID + c];
        accH.x += h0.x + h1.x; accH.y += h0.y + h1.y;
        accH.z += h0.z + h1.z; accH.w += h0.w + h1.w;
        accE.x += fmaxf(p0.x + qb.x, 0.f) + fmaxf(p1.x + qb.x, 0.f);
        accE.y += fmaxf(p0.y + qb.y, 0.f) + fmaxf(p1.y + qb.y, 0.f);
        accE.z += fmaxf(p0.z + qb.z, 0.f) + fmaxf(p1.z + qb.z, 0.f);
        accE.w += fmaxf(p0.w + qb.w, 0.f) + fmaxf(p1.w + qb.w, 0.f);
    }
    if (i < end) {
        int ua = g_eu[i];
        float4 h0 = *(const float4*)&g_hn1[(size_t)ua * HID + c];
        float4 p0 = *(const float4*)&g_P  [(size_t)ua * HID + c];
        accH.x += h0.x; accH.y += h0.y; accH.z += h0.z; accH.w += h0.w;
        accE.x += fmaxf(p0.x + qb.x, 0.f);
        accE.y += fmaxf(p0.y + qb.y, 0.f);
        accE.z += fmaxf(p0.z + qb.z, 0.f);
        accE.w += fmaxf(p0.w + qb.w, 0.f);
    }
    *(float4*)&g_msum2[(size_t)node * 256 + c]       = accH;
    *(float4*)&g_msum2[(size_t)node * 256 + 128 + c] = accE;
}

// ================= fused node_apply + P/Q projection =================
// Phase A: hn_out = relu(concat(hn_in, msum*rdeg) @ Wa + ba)   [proven NPB=16 shape]
// Phase B: P = hn_out @ We_top + be;  Q = hn_out @ We_bot      [from smem tile]
// Phase-B input tile overlays phase-A's xs buffer (sync-guarded) -> smem stays K*18 floats.
template <int KN, int KM>
__global__ void __launch_bounds__(128)
fused_node_pq_kernel(const float* __restrict__ hn_in,
                     const float* __restrict__ msum,
                     const float* __restrict__ Wa,
                     const float* __restrict__ ba,
                     const float* __restrict__ We,   // [256,128] row-major
                     const float* __restrict__ be,
                     float* __restrict__ hn_out,
                     float* __restrict__ P,
                     float* __restrict__ Q) {
    constexpr int K = KN + KM;
    constexpr int NPB = 16;
    __shared__ float smem_buf[K * 18];     // phase A: [K][18]; phase B reuses rows 0..127
    __shared__ float rdeg_s[NPB];
    float (*xs)[18] = (float(*)[18])smem_buf;
    int n0 = blockIdx.x * NPB;
    int tid = threadIdx.x;

    if (tid < NPB) {
        int n = n0 + tid;
        float d = (float)max(g_rowptr[n + 1] - g_rowptr[n], 1);
        rdeg_s[tid] = 1.0f / d;
    }
    __syncthreads();

    for (int idx = tid; idx < NPB * K; idx += 128) {
        int ni = idx / K;
        int k  = idx % K;
        int n  = n0 + ni;
        float val;
        if (k < KN) val = hn_in[(size_t)n * KN + k];
        else        val = msum[(size_t)n * KM + (k - KN)] * rdeg_s[ni];
        xs[k][ni] = val;
    }
    __syncthreads();

    int grp = tid >> 6;
    int jt  = tid & 63;

    // ---- phase A GEMM ----
    {
        float b0 = ba[jt], b1 = ba[jt + 64];
        ull a0[4], a1[4];
        #pragma unroll
        for (int i = 0; i < 4; i++) { a0[i] = pk2(b0, b0); a1[i] = pk2(b1, b1); }

        const float* Wj = Wa + jt;
        #pragma unroll 4
        for (int k = 0; k < K; k++) {
            float w0 = Wj[k * HID];
            float w1 = Wj[k * HID + 64];
            ull w0d = pk2(w0, w0);
            ull w1d = pk2(w1, w1);
            ull xp[4];
            #pragma unroll
            for (int i = 0; i < 4; i++)
                xp[i] = *(const ull*)&xs[k][grp * 8 + 2 * i];
            #pragma unroll
            for (int i = 0; i < 4; i++) {
                FFMA2(a0[i], xp[i], w0d, a0[i]);
                FFMA2(a1[i], xp[i], w1d, a1[i]);
            }
        }
        __syncthreads();   // all phase-A reads of xs done before overwrite

        #pragma unroll
        for (int i = 0; i < 4; i++) {
            float x0, x1, y0, y1;
            upk2(a0[i], x0, x1);
            upk2(a1[i], y0, y1);
            x0 = fmaxf(x0, 0.f); x1 = fmaxf(x1, 0.f);
            y0 = fmaxf(y0, 0.f); y1 = fmaxf(y1, 0.f);
            int nl = grp * 8 + 2 * i;
            size_t n = (size_t)(n0 + nl);
            hn_out[n * HID + jt]            = x0;
            hn_out[(n + 1) * HID + jt]      = x1;
            hn_out[n * HID + jt + 64]       = y0;
            hn_out[(n + 1) * HID + jt + 64] = y1;
            xs[jt][nl] = x0;       xs[jt][nl + 1] = x1;
            xs[jt + 64][nl] = y0;  xs[jt + 64][nl + 1] = y1;
        }
    }
    __syncthreads();

    // ---- phase B GEMM (pq) from smem tile ----
    {
        float be0 = be[jt], be1 = be[jt + 64];
        ull p0[4], p1[4], q0[4], q1[4];
        #pragma unroll
        for (int i = 0; i < 4; i++) {
            p0[i] = pk2(be0, be0);
            p1[i] = pk2(be1, be1);
            q0[i] = 0ull; q1[i] = 0ull;
        }

        const float* Wj = We + jt;
        #pragma unroll 2
        for (int k = 0; k < HID; k++) {
            float wt0 = Wj[k * HID];
            float wt1 = Wj[k * HID + 64];
            float wb0 = Wj[(k + HID) * HID];
            float wb1 = Wj[(k + HID) * HID + 64];
            ull wt0d = pk2(wt0, wt0);
            ull wt1d = pk2(wt1, wt1);
            ull wb0d = pk2(wb0, wb0);
            ull wb1d = pk2(wb1, wb1);
            ull xp[4];
            #pragma unroll
            for (int i = 0; i < 4; i++)
                xp[i] = *(const ull*)&xs[k][grp * 8 + 2 * i];
            #pragma unroll
            for (int i = 0; i < 4; i++) {
                FFMA2(p0[i], xp[i], wt0d, p0[i]);
                FFMA2(p1[i], xp[i], wt1d, p1[i]);
                FFMA2(q0[i], xp[i], wb0d, q0[i]);
                FFMA2(q1[i], xp[i], wb1d, q1[i]);
            }
        }
        #pragma unroll
        for (int i = 0; i < 4; i++) {
            float x0, x1;
            size_t n = (size_t)(n0 + grp * 8 + 2 * i);
            upk2(p0[i], x0, x1); P[n * HID + jt]      = x0; P[(n + 1) * HID + jt]      = x1;
            upk2(p1[i], x0, x1); P[n * HID + jt + 64] = x0; P[(n + 1) * HID + jt + 64] = x1;
            upk2(q0[i], x0, x1); Q[n * HID + jt]      = x0; Q[(n + 1) * HID + jt]      = x1;
            upk2(q1[i], x0, x1); Q[n * HID + jt + 64] = x0; Q[(n + 1) * HID + jt + 64] = x1;
        }
    }
}

// ================= layer-2 edge via CSR (unroll-2, occ-pinned) =================
__global__ void __launch_bounds__(256, 8)
edge2_csr_kernel(float* __restrict__ he2) {
    int gtid = blockIdx.x * blockDim.x + threadIdx.x;
    int node = gtid >> 5;
    int lane = gtid & 31;
    if (node >= N_NODES) return;
    int beg = g_rowptr[node], end = g_rowptr[node + 1];
    int c = lane * 4;

    float4 qb = *(const float4*)&g_Q[(size_t)node * HID + c];

    int i = beg;
    for (; i + 1 < end; i += 2) {
        int ua = g_eu[i],  ea = g_eid[i];
        int ub = g_eu[i + 1], eb = g_eid[i + 1];
        float4 pa = *(const float4*)&g_P[(size_t)ua * HID + c];
        float4 pb = *(const float4*)&g_P[(size_t)ub * HID + c];
        float4 ha, hb;
        ha.x = fmaxf(pa.x + qb.x, 0.f); ha.y = fmaxf(pa.y + qb.y, 0.f);
        ha.z = fmaxf(pa.z + qb.z, 0.f); ha.w = fmaxf(pa.w + qb.w, 0.f);
        hb.x = fmaxf(pb.x + qb.x, 0.f); hb.y = fmaxf(pb.y + qb.y, 0.f);
        hb.z = fmaxf(pb.z + qb.z, 0.f); hb.w = fmaxf(pb.w + qb.w, 0.f);
        *(float4*)&he2[(size_t)ea * HID + c] = ha;
        *(float4*)&he2[(size_t)eb * HID + c] = hb;
    }
    if (i < end) {
        int ua = g_eu[i], ea = g_eid[i];
        float4 pa = *(const float4*)&g_P[(size_t)ua * HID + c];
        float4 ha;
        ha.x = fmaxf(pa.x + qb.x, 0.f); ha.y = fmaxf(pa.y + qb.y, 0.f);
        ha.z = fmaxf(pa.z + qb.z, 0.f); ha.w = fmaxf(pa.w + qb.w, 0.f);
        *(float4*)&he2[(size_t)ea * HID + c] = ha;
    }
}

// ---------------- launch ----------------
extern "C" void kernel_launch(void* const* d_in, const int* in_sizes, int n_in,
                              void* d_out, int out_size) {
    const float* nfeats = (const float*)d_in[0];
    const float* efeats = (const float*)d_in[1];
    const float* W1a_w  = (const float*)d_in[2];
    const float* W1a_b  = (const float*)d_in[3];
    const float* W1e_w  = (const float*)d_in[4];
    const float* W1e_b  = (const float*)d_in[5];
    const float* W2a_w  = (const float*)d_in[6];
    const float* W2a_b  = (const float*)d_in[7];
    const float* W2e_w  = (const float*)d_in[8];
    const float* W2e_b  = (const float*)d_in[9];
    const int*   u      = (const int*)d_in[10];
    const int*   v      = (const int*)d_in[11];

    float* out = (float*)d_out;
    float* hn2 = out;                          // [N, 128]
    float* he2 = out + (size_t)N_NODES * HID;  // [E, 128]

    void *p_cnt, *p_rowptr, *p_cursor, *p_m1, *p_m2, *p_hn1, *p_P, *p_Q;
    cudaGetSymbolAddress(&p_cnt,    g_cnt);
    cudaGetSymbolAddress(&p_rowptr, g_rowptr);
    cudaGetSymbolAddress(&p_cursor, g_cursor);
    cudaGetSymbolAddress(&p_m1,     g_msum1);
    cudaGetSymbolAddress(&p_m2,     g_msum2);
    cudaGetSymbolAddress(&p_hn1,    g_hn1);
    cudaGetSymbolAddress(&p_P,      g_P);
    cudaGetSymbolAddress(&p_Q,      g_Q);
    float* msum1 = (float*)p_m1;
    float* msum2 = (float*)p_m2;
    float* hn1   = (float*)p_hn1;
    float* P     = (float*)p_P;
    float* Q     = (float*)p_Q;

    const int EBLK  = (N_EDGES + 255) / 256;
    const int NWBLK = (N_NODES * 32 + 255) / 256;
    const int GBLK  = N_NODES / 16;            // 3125

    // ---- CSR build ----
    cudaMemsetAsync(p_cnt, 0, sizeof(int) * N_NODES, 0);
    cnt_kernel<<<EBLK, 256>>>(v);
    scan_kernel<<<1, 256>>>();
    cudaMemcpyAsync(p_cursor, p_rowptr, sizeof(int) * N_NODES,
                    cudaMemcpyDeviceToDevice, 0);
    fill_kernel<<<EBLK, 256>>>(u, v);

    // ---- layer 1 ----
    agg1_kernel<<<NWBLK, 256>>>(nfeats, efeats);
    fused_node_pq_kernel<ND_IN, ND_IN + ED_IN><<<GBLK, 128>>>(
        nfeats, msum1, W1a_w, W1a_b, W1e_w, W1e_b, hn1, P, Q);
    agg2_kernel<<<NWBLK, 256>>>();

    // ---- layer 2 ----
    fused_node_pq_kernel<HID, 2 * HID><<<GBLK, 128>>>(
        hn1, msum2, W2a_w, W2a_b, W2e_w, W2e_b, hn2, P, Q);
    edge2_csr_kernel<<<NWBLK, 256>>>(he2);
}